// round 15
// baseline (speedup 1.0000x reference)
#include <cuda_runtime.h>
#include <cstdint>

// Problem constants
#define B_   256
#define T_   512
#define IDIM 64
#define H_   256
#define G4   1024              // 4*H
#define BT   (B_ * T_)

typedef unsigned long long u64;

// ---------------- scratch (device globals; no allocs allowed) ----------------
__device__ float g_xg[BT * G4];        // gate pre-activations (column-permuted cc = v*4+g)
__device__ float g_h1[BT * H_];        // layer-0 hidden states, layout [t][b][v]
__device__ float g_hbuf[2 * H_ * B_];  // ping-pong h, layout [buf][v][b]
__device__ float g_last[B_ * H_];      // final h2, [b][v]
__device__ float g_weff[4 * H_];       // collapsed head weight (W2@W1)
__device__ float g_beff[4];            // collapsed head bias

// ---------------- packed dual-fp32 FMA (SASS FFMA2) ----------------
__device__ __forceinline__ void ffma2(u64& d, u64 a, u64 b) {
    asm("fma.rn.f32x2 %0, %1, %2, %0;" : "+l"(d) : "l"(a), "l"(b));
}
__device__ __forceinline__ u64 pack2(float x, float y) {
    u64 r; asm("mov.b64 %0, {%1, %2};" : "=l"(r) : "f"(x), "f"(y)); return r;
}
__device__ __forceinline__ u64 dup2(float x) {
    u64 r; asm("mov.b64 %0, {%1, %1};" : "=l"(r) : "f"(x)); return r;
}
__device__ __forceinline__ void unpack2(u64 v, float& x, float& y) {
    asm("mov.b64 {%0, %1}, %2;" : "=f"(x), "=f"(y) : "l"(v));
}

// ---------------- activations ----------------
__device__ __forceinline__ float sigm_(float x) {
    return 1.0f / (1.0f + __expf(-x));
}
__device__ __forceinline__ float tanh_(float x) {
    return 2.0f / (1.0f + __expf(-2.0f * x)) - 1.0f;
}

// ---------------- GEMM: C[M][1024] = A[M][K] @ Wperm^T + bias_perm ----------------
// Output column cc = v*4 + g maps to original weight row (cc&3)*256 + (cc>>2).
// Tiles 128x128x16, 256 threads, 8x8 microtile computed as 8x(4 f32x2) FFMA2.
__global__ void __launch_bounds__(256) gemm_bias_kernel(
    const float* __restrict__ A, const float* __restrict__ W,
    const float* __restrict__ bA, const float* __restrict__ bB,
    float* __restrict__ C, int K)
{
    __shared__ float As[16][132];
    __shared__ float Ws[16][132];
    const int tid = threadIdx.x;
    const int tx = tid & 15;
    const int ty = tid >> 4;
    const int m0 = blockIdx.y * 128;
    const int n0 = blockIdx.x * 128;

    u64 acc2[8][4];
#pragma unroll
    for (int i = 0; i < 8; i++)
#pragma unroll
        for (int j = 0; j < 4; j++) acc2[i][j] = 0ull;

    const int lr = tid >> 2;            // 0..63
    const int lk = (tid & 3) << 2;      // 0,4,8,12
    const float* Ab = A + (size_t)m0 * K;

    // permuted W row for this thread's two tile rows
    int grow[2];
#pragma unroll
    for (int h = 0; h < 2; h++) {
        int cc = n0 + lr + 64 * h;
        grow[h] = ((cc & 3) << 8) + (cc >> 2);
    }

    float4 av[2], wv[2];
#pragma unroll
    for (int h = 0; h < 2; h++) {
        int r = lr + 64 * h;
        av[h] = *(const float4*)(Ab + (size_t)r * K + lk);
        wv[h] = *(const float4*)(W + (size_t)grow[h] * K + lk);
    }

    for (int k0 = 0; k0 < K; k0 += 16) {
#pragma unroll
        for (int h = 0; h < 2; h++) {
            int r = lr + 64 * h;
            As[lk + 0][r] = av[h].x; As[lk + 1][r] = av[h].y;
            As[lk + 2][r] = av[h].z; As[lk + 3][r] = av[h].w;
            Ws[lk + 0][r] = wv[h].x; Ws[lk + 1][r] = wv[h].y;
            Ws[lk + 2][r] = wv[h].z; Ws[lk + 3][r] = wv[h].w;
        }
        __syncthreads();
        if (k0 + 16 < K) {
            int kn = k0 + 16;
#pragma unroll
            for (int h = 0; h < 2; h++) {
                int r = lr + 64 * h;
                av[h] = *(const float4*)(Ab + (size_t)r * K + kn + lk);
                wv[h] = *(const float4*)(W + (size_t)grow[h] * K + kn + lk);
            }
        }
#pragma unroll
        for (int k = 0; k < 16; k++) {
            float a[8];
            *(float4*)(a)     = *(const float4*)(&As[k][ty * 8]);
            *(float4*)(a + 4) = *(const float4*)(&As[k][ty * 8 + 4]);
            ulonglong2 w01 = *(const ulonglong2*)(&Ws[k][tx * 8]);
            ulonglong2 w23 = *(const ulonglong2*)(&Ws[k][tx * 8 + 4]);
#pragma unroll
            for (int i = 0; i < 8; i++) {
                u64 ad = dup2(a[i]);
                ffma2(acc2[i][0], ad, w01.x);
                ffma2(acc2[i][1], ad, w01.y);
                ffma2(acc2[i][2], ad, w23.x);
                ffma2(acc2[i][3], ad, w23.y);
            }
        }
        __syncthreads();
    }

    float bias[8];
#pragma unroll
    for (int j = 0; j < 8; j++) {
        int cc = n0 + tx * 8 + j;
        int orig = ((cc & 3) << 8) + (cc >> 2);
        bias[j] = bA[orig] + bB[orig];
    }
#pragma unroll
    for (int i = 0; i < 8; i++) {
        int row = m0 + ty * 8 + i;
        float* cp = C + (size_t)row * G4 + n0 + tx * 8;
        float o[8];
#pragma unroll
        for (int j = 0; j < 4; j++) unpack2(acc2[i][j], o[2 * j], o[2 * j + 1]);
        float4 o0 = make_float4(o[0] + bias[0], o[1] + bias[1],
                                o[2] + bias[2], o[3] + bias[3]);
        float4 o1 = make_float4(o[4] + bias[4], o[5] + bias[5],
                                o[6] + bias[6], o[7] + bias[7]);
        *(float4*)cp = o0;
        *(float4*)(cp + 4) = o1;
    }
}

// ---------------- LSTM scan ----------------
// Grid (8, 16), cluster (8,1,1), 512 threads. blockIdx.y = batch group (16 rows),
// blockIdx.x = slice s: CTA owns hidden units [s*32, s*32+32) = 128 gate rows,
// weight columns in cc-order (unit*4 + gate). Each thread owns all 4 gates of one
// (unit, batch) pair; accumulators are two f32x2 pairs -> 2 FFMA2 per k.
// h stored in SMEM pre-duplicated as (h,h) u64 so no per-k packing is needed.
#define SCAN_SMEM ((256 * 128 + 256 * 16 * 2 + 32 * 17) * 4)

__global__ void __launch_bounds__(512, 1) __cluster_dims__(8, 1, 1)
lstm_scan_kernel(const float* __restrict__ xg, const float* __restrict__ Whh,
                 float* __restrict__ h_arch, float* __restrict__ h_last,
                 int rowmode)   // 0: row = b*T+t (layer0), 1: row = t*B+b (layer1)
{
    extern __shared__ float sm[];
    float* w_s = sm;                              // [k=256][c=128], c = u*4+g
    u64*   h2  = (u64*)(sm + 256 * 128);          // [k=256][b=16] duplicated pairs
    float* a_s = sm + 256 * 128 + 256 * 16 * 2;   // [u=32][b stride 17] archive staging

    const int s   = blockIdx.x;           // 0..7
    const int gb0 = blockIdx.y * 16;      // batch base
    const int tid = threadIdx.x;
    const int tx  = tid & 15;             // local batch
    const int ty  = tid >> 4;             // local unit 0..31

    // Load weight slice (cc-order) into SMEM once.
    for (int idx = tid; idx < 128 * 64; idx += 512) {
        int c  = idx >> 6;
        int kq = (idx & 63) << 2;
        int gr = ((c & 3) << 8) + s * 32 + (c >> 2);  // gate*256 + global unit
        float4 v = *(const float4*)(Whh + (size_t)gr * 256 + kq);
        w_s[(kq + 0) * 128 + c] = v.x;
        w_s[(kq + 1) * 128 + c] = v.y;
        w_s[(kq + 2) * 128 + c] = v.z;
        w_s[(kq + 3) * 128 + c] = v.w;
    }
    // Zero h(0) in our slice of ping buffer 0 (one value per thread).
    g_hbuf[(s * 32 + ty) * 256 + gb0 + tx] = 0.f;

    float cstate = 0.f;
    const int xcol = s * 128 + ty * 4;

    __threadfence();
    asm volatile("barrier.cluster.arrive.aligned;\n" ::: "memory");
    asm volatile("barrier.cluster.wait.aligned;\n" ::: "memory");

    for (int t = 0; t < T_; t++) {
        const int cur = t & 1;

        // xg prefetch: consumed only AFTER the k-loop -> full k-loop of slack.
        size_t row = rowmode ? ((size_t)t * 256 + gb0 + tx)
                             : ((size_t)(gb0 + tx) * T_ + t);
        float4 xv = *(const float4*)(xg + row * (size_t)G4 + xcol);

        // Phase A: load h(t-1) tile [256 x 16] from L2, store duplicated pairs
        const float* hb = g_hbuf + cur * (H_ * B_);
#pragma unroll
        for (int i = 0; i < 8; i++) {
            int k = i * 32 + ty;
            float hv = __ldcg(hb + k * 256 + gb0 + tx);
            h2[k * 16 + tx] = dup2(hv);
        }
        __syncthreads();

        // Phase B: 4 gates of (unit ty, batch tx) over k=256, 2 FFMA2 per k
        u64 A01 = 0ull, A23 = 0ull;
#pragma unroll 8
        for (int k = 0; k < 256; k++) {
            u64 hv2 = h2[k * 16 + tx];
            ulonglong2 w2 = *(const ulonglong2*)(w_s + k * 128 + ty * 4);
            ffma2(A01, hv2, w2.x);
            ffma2(A23, hv2, w2.y);
        }
        float a0, a1, a2, a3;
        unpack2(A01, a0, a1);
        unpack2(A23, a2, a3);
        a0 += xv.x; a1 += xv.y; a2 += xv.z; a3 += xv.w;

        // Phase C: gate math directly on accumulators
        float iv = sigm_(a0);
        float fv = sigm_(a1);
        float gv = tanh_(a2);
        float ov = sigm_(a3);
        cstate = fv * cstate + iv * gv;
        float hh = ov * tanh_(cstate);

        float* hn = g_hbuf + (cur ^ 1) * (H_ * B_);
        hn[(s * 32 + ty) * 256 + gb0 + tx] = hh;   // coalesced 64B chunks

        if (h_arch) {
            // stage through SMEM for coalesced [t][b][v] writes
            a_s[ty * 17 + tx] = hh;
            __syncthreads();
            int b2 = tid >> 5, u2 = tid & 31;
            h_arch[((size_t)t * 256 + gb0 + b2) * H_ + s * 32 + u2] = a_s[u2 * 17 + b2];
        }
        if (h_last && t == T_ - 1)
            h_last[(gb0 + tx) * H_ + s * 32 + ty] = hh;

        // Release h(t) + sync all 8 CTAs of the cluster (also acts as CTA barrier)
        asm volatile("barrier.cluster.arrive.aligned;\n" ::: "memory");
        asm volatile("barrier.cluster.wait.aligned;\n" ::: "memory");
    }
}

// ---------------- head: collapse W2@(W1 . + b1) + b2 into one linear map ----------------
__global__ void __launch_bounds__(256) head_pre_kernel(
    const float* __restrict__ W1, const float* __restrict__ b1,
    const float* __restrict__ W2, const float* __restrict__ b2)
{
    __shared__ float w2s[4 * 1280];
    const int tid = threadIdx.x;   // = hidden index h
    for (int idx = tid; idx < 4 * 1280; idx += 256) w2s[idx] = W2[idx];
    __syncthreads();

    float acc[4] = {0.f, 0.f, 0.f, 0.f};
    for (int j = 0; j < 1280; j++) {
        float w1v = W1[(size_t)j * 256 + tid];
#pragma unroll
        for (int o = 0; o < 4; o++) acc[o] = fmaf(w2s[o * 1280 + j], w1v, acc[o]);
    }
#pragma unroll
    for (int o = 0; o < 4; o++) g_weff[o * 256 + tid] = acc[o];

    if (tid < 4) {
        float bb = b2[tid];
        for (int j = 0; j < 1280; j++) bb = fmaf(w2s[tid * 1280 + j], b1[j], bb);
        g_beff[tid] = bb;
    }
}

__global__ void __launch_bounds__(256) head_final_kernel(float* __restrict__ out)
{
    int id = blockIdx.x * 256 + threadIdx.x;  // 0..1023
    int b = id >> 2, o = id & 3;
    float acc = g_beff[o];
    const float* lp = g_last + b * 256;
    const float* wp = g_weff + o * 256;
    for (int h = 0; h < 256; h++) acc = fmaf(lp[h], wp[h], acc);
    out[id] = acc;   // y[b][o], row-major [256,4]
}

// ---------------- launch ----------------
extern "C" void kernel_launch(void* const* d_in, const int* in_sizes, int n_in,
                              void* d_out, int out_size)
{
    const float* x    = (const float*)d_in[0];
    const float* Wih0 = (const float*)d_in[1];
    const float* Whh0 = (const float*)d_in[2];
    const float* bih0 = (const float*)d_in[3];
    const float* bhh0 = (const float*)d_in[4];
    const float* Wih1 = (const float*)d_in[5];
    const float* Whh1 = (const float*)d_in[6];
    const float* bih1 = (const float*)d_in[7];
    const float* bhh1 = (const float*)d_in[8];
    const float* W1   = (const float*)d_in[9];
    const float* b1   = (const float*)d_in[10];
    const float* W2   = (const float*)d_in[11];
    const float* b2   = (const float*)d_in[12];
    float* out = (float*)d_out;

    float *p_xg, *p_h1, *p_last;
    cudaGetSymbolAddress((void**)&p_xg, g_xg);
    cudaGetSymbolAddress((void**)&p_h1, g_h1);
    cudaGetSymbolAddress((void**)&p_last, g_last);

    cudaFuncSetAttribute(lstm_scan_kernel,
                         cudaFuncAttributeMaxDynamicSharedMemorySize, SCAN_SMEM);

    dim3 gemmGrid(8, 1024);  // N tiles x M tiles (M = 131072)
    dim3 scanGrid(8, 16);    // 8-CTA clusters x 16 batch groups

    // Layer 0: input projection (rows b*T+t), then scan (archives h1 as [t][b][v])
    gemm_bias_kernel<<<gemmGrid, 256>>>(x, Wih0, bih0, bhh0, p_xg, IDIM);
    lstm_scan_kernel<<<scanGrid, 512, SCAN_SMEM>>>(p_xg, Whh0, p_h1, nullptr, 0);

    // Layer 1: projection from h1 (rows t*B+b), then scan (keeps only last h)
    gemm_bias_kernel<<<gemmGrid, 256>>>(p_h1, Wih1, bih1, bhh1, p_xg, H_);
    lstm_scan_kernel<<<scanGrid, 512, SCAN_SMEM>>>(p_xg, Whh1, nullptr, p_last, 1);

    // Collapsed linear head
    head_pre_kernel<<<1, 256>>>(W1, b1, W2, b2);
    head_final_kernel<<<4, 256>>>(out);
}

// round 17
// speedup vs baseline: 1.3413x; 1.3413x over previous
#include <cuda_runtime.h>
#include <cstdint>

// Problem constants
#define B_   256
#define T_   512
#define IDIM 64
#define H_   256
#define G4   1024              // 4*H
#define BT   (B_ * T_)

// ---------------- scratch (device globals; no allocs allowed) ----------------
__device__ float g_xg[BT * G4];        // gate pre-activations (column-permuted cc = v*4+g)
__device__ float g_h1[BT * H_];        // layer-0 hidden states, layout [t][b][v]
__device__ float g_hbuf[2 * H_ * B_];  // ping-pong h, layout [buf][v][b]
__device__ float g_last[B_ * H_];      // final h2, [b][v]
__device__ float g_weff[4 * H_];       // collapsed head weight (W2@W1)
__device__ float g_beff[4];            // collapsed head bias

// ---------------- activations ----------------
__device__ __forceinline__ float sigm_(float x) {
    return 1.0f / (1.0f + __expf(-x));
}
__device__ __forceinline__ float tanh_(float x) {
    return 2.0f / (1.0f + __expf(-2.0f * x)) - 1.0f;
}

// ---------------- GEMM: C[M][1024] = A[M][K] @ Wperm^T + bias_perm ----------------
// Output column cc = v*4 + g maps to original weight row (cc&3)*256 + (cc>>2).
// Tiles 128x128x16, 256 threads, 8x8 microtile, register double-buffered k-tiles.
__global__ void __launch_bounds__(256) gemm_bias_kernel(
    const float* __restrict__ A, const float* __restrict__ W,
    const float* __restrict__ bA, const float* __restrict__ bB,
    float* __restrict__ C, int K)
{
    __shared__ float As[16][132];
    __shared__ float Ws[16][132];
    const int tid = threadIdx.x;
    const int tx = tid & 15;
    const int ty = tid >> 4;
    const int m0 = blockIdx.y * 128;
    const int n0 = blockIdx.x * 128;

    float acc[8][8];
#pragma unroll
    for (int i = 0; i < 8; i++)
#pragma unroll
        for (int j = 0; j < 8; j++) acc[i][j] = 0.f;

    const int lr = tid >> 2;            // 0..63
    const int lk = (tid & 3) << 2;      // 0,4,8,12
    const float* Ab = A + (size_t)m0 * K;

    // permuted W row for this thread's two tile rows
    int grow[2];
#pragma unroll
    for (int h = 0; h < 2; h++) {
        int cc = n0 + lr + 64 * h;
        grow[h] = ((cc & 3) << 8) + (cc >> 2);
    }

    float4 av[2], wv[2];
#pragma unroll
    for (int h = 0; h < 2; h++) {
        int r = lr + 64 * h;
        av[h] = *(const float4*)(Ab + (size_t)r * K + lk);
        wv[h] = *(const float4*)(W + (size_t)grow[h] * K + lk);
    }

    for (int k0 = 0; k0 < K; k0 += 16) {
#pragma unroll
        for (int h = 0; h < 2; h++) {
            int r = lr + 64 * h;
            As[lk + 0][r] = av[h].x; As[lk + 1][r] = av[h].y;
            As[lk + 2][r] = av[h].z; As[lk + 3][r] = av[h].w;
            Ws[lk + 0][r] = wv[h].x; Ws[lk + 1][r] = wv[h].y;
            Ws[lk + 2][r] = wv[h].z; Ws[lk + 3][r] = wv[h].w;
        }
        __syncthreads();
        if (k0 + 16 < K) {
            int kn = k0 + 16;
#pragma unroll
            for (int h = 0; h < 2; h++) {
                int r = lr + 64 * h;
                av[h] = *(const float4*)(Ab + (size_t)r * K + kn + lk);
                wv[h] = *(const float4*)(W + (size_t)grow[h] * K + kn + lk);
            }
        }
#pragma unroll
        for (int k = 0; k < 16; k++) {
            float a[8], w[8];
            *(float4*)(a)     = *(const float4*)(&As[k][ty * 8]);
            *(float4*)(a + 4) = *(const float4*)(&As[k][ty * 8 + 4]);
            *(float4*)(w)     = *(const float4*)(&Ws[k][tx * 8]);
            *(float4*)(w + 4) = *(const float4*)(&Ws[k][tx * 8 + 4]);
#pragma unroll
            for (int i = 0; i < 8; i++)
#pragma unroll
                for (int j = 0; j < 8; j++)
                    acc[i][j] = fmaf(a[i], w[j], acc[i][j]);
        }
        __syncthreads();
    }

    float bias[8];
#pragma unroll
    for (int j = 0; j < 8; j++) {
        int cc = n0 + tx * 8 + j;
        int orig = ((cc & 3) << 8) + (cc >> 2);
        bias[j] = bA[orig] + bB[orig];
    }
#pragma unroll
    for (int i = 0; i < 8; i++) {
        int row = m0 + ty * 8 + i;
        float* cp = C + (size_t)row * G4 + n0 + tx * 8;
        float4 o0 = make_float4(acc[i][0] + bias[0], acc[i][1] + bias[1],
                                acc[i][2] + bias[2], acc[i][3] + bias[3]);
        float4 o1 = make_float4(acc[i][4] + bias[4], acc[i][5] + bias[5],
                                acc[i][6] + bias[6], acc[i][7] + bias[7]);
        *(float4*)cp = o0;
        *(float4*)(cp + 4) = o1;
    }
}

// ---------------- LSTM scan ----------------
// Grid (8, 16), cluster (8,1,1), 512 threads. blockIdx.y = batch group (16),
// blockIdx.x = slice s: CTA owns hidden units [s*32, s*32+32) = 128 gate rows
// in cc-order (unit*4 + gate). Thread decomposition: (k-half, unit, batch-pair):
//   kh = tid>>8, ty = (tid>>3)&31 (unit), tx = tid&7 (batches 2tx, 2tx+1)
// 8 accumulators per thread (4 gates x 2 batches), k-range of 128.
// Inner loop: 1 LDS.64 (h pair) + 1 LDS.128 (w) + 8 FFMA -> FFMA-dominant 2:1.
// kh=1 warps prefetch xg and fold it into their partial before the split-k
// reduction through SMEM.
// NOTE: archive staging uses stride 18 (EVEN) so float2 stores stay 8B-aligned.
#define SCAN_SMEM ((256 * 128 + 256 * 16 + 256 * 8 + 32 * 18) * 4)

__global__ void __launch_bounds__(512, 1) __cluster_dims__(8, 1, 1)
lstm_scan_kernel(const float* __restrict__ xg, const float* __restrict__ Whh,
                 float* __restrict__ h_arch, float* __restrict__ h_last,
                 int rowmode)   // 0: row = b*T+t (layer0), 1: row = t*B+b (layer1)
{
    extern __shared__ float sm[];
    float* w_s   = sm;                                   // [k=256][c=128]
    float* h_s   = sm + 256 * 128;                       // [k=256][b=16]
    float* red_s = sm + 256 * 128 + 256 * 16;            // [256 threads][8]
    float* a_s   = sm + 256 * 128 + 256 * 16 + 256 * 8;  // [u=32][b stride 18]

    const int s   = blockIdx.x;           // 0..7
    const int gb0 = blockIdx.y * 16;      // batch base
    const int tid = threadIdx.x;
    const int kh  = tid >> 8;             // k-half 0/1 (warps 0-7 vs 8-15)
    const int rem = tid & 255;
    const int tx  = rem & 7;              // batch pair -> batches 2tx, 2tx+1
    const int ty  = (rem >> 3) & 31;      // local unit 0..31
    const int kbase = kh << 7;            // 0 or 128

    // Load weight slice (cc-order) into SMEM once.
    for (int idx = tid; idx < 128 * 64; idx += 512) {
        int c  = idx >> 6;
        int kq = (idx & 63) << 2;
        int gr = ((c & 3) << 8) + s * 32 + (c >> 2);  // gate*256 + global unit
        float4 v = *(const float4*)(Whh + (size_t)gr * 256 + kq);
        w_s[(kq + 0) * 128 + c] = v.x;
        w_s[(kq + 1) * 128 + c] = v.y;
        w_s[(kq + 2) * 128 + c] = v.z;
        w_s[(kq + 3) * 128 + c] = v.w;
    }
    // Zero h(0): 512 values, one per thread.
    {
        int u = tid >> 4, b = tid & 15;
        g_hbuf[(s * 32 + u) * 256 + gb0 + b] = 0.f;
    }

    // c-state lives in kh==0 threads: 2 batches per thread.
    float c0 = 0.f, c1 = 0.f;
    const int xcol = s * 128 + ty * 4;

    __threadfence();
    asm volatile("barrier.cluster.arrive.aligned;\n" ::: "memory");
    asm volatile("barrier.cluster.wait.aligned;\n" ::: "memory");

    for (int t = 0; t < T_; t++) {
        const int cur = t & 1;

        // kh=1 warps prefetch xg for both batches (consumed after k-loop).
        float4 xv0, xv1;
        if (kh) {
            size_t r0 = rowmode ? ((size_t)t * 256 + gb0 + 2 * tx)
                                : ((size_t)(gb0 + 2 * tx) * T_ + t);
            size_t r1 = rowmode ? (r0 + 1) : (r0 + T_);
            xv0 = *(const float4*)(xg + r0 * (size_t)G4 + xcol);
            xv1 = *(const float4*)(xg + r1 * (size_t)G4 + xcol);
        }

        // Phase A: all threads load h(t-1) tile [256 x 16] from L2.
        const float* hb = g_hbuf + cur * (H_ * B_);
#pragma unroll
        for (int i = 0; i < 8; i++) {
            int idx = i * 512 + tid;
            int k = idx >> 4, b = idx & 15;
            h_s[k * 16 + b] = __ldcg(hb + k * 256 + gb0 + b);
        }
        __syncthreads();

        // Phase B: partial gates over this thread's k-half.
        float a0 = 0.f, a1 = 0.f, a2 = 0.f, a3 = 0.f;  // batch 2tx
        float a4 = 0.f, a5 = 0.f, a6 = 0.f, a7 = 0.f;  // batch 2tx+1
        const float* hp = h_s + kbase * 16 + 2 * tx;
        const float* wp = w_s + kbase * 128 + ty * 4;
#pragma unroll 8
        for (int k = 0; k < 128; k++) {
            float2 hv = *(const float2*)(hp + k * 16);
            float4 w  = *(const float4*)(wp + k * 128);
            a0 = fmaf(hv.x, w.x, a0);
            a1 = fmaf(hv.x, w.y, a1);
            a2 = fmaf(hv.x, w.z, a2);
            a3 = fmaf(hv.x, w.w, a3);
            a4 = fmaf(hv.y, w.x, a4);
            a5 = fmaf(hv.y, w.y, a5);
            a6 = fmaf(hv.y, w.z, a6);
            a7 = fmaf(hv.y, w.w, a7);
        }

        // Split-k reduce: kh=1 folds xg into its partial and stores to SMEM.
        if (kh) {
            float* rp = red_s + rem * 8;
            *(float4*)(rp)     = make_float4(a0 + xv0.x, a1 + xv0.y,
                                             a2 + xv0.z, a3 + xv0.w);
            *(float4*)(rp + 4) = make_float4(a4 + xv1.x, a5 + xv1.y,
                                             a6 + xv1.z, a7 + xv1.w);
        }
        __syncthreads();

        // Phase C (kh=0 only): combine halves, gate math, publish h(t).
        if (!kh) {
            const float* rp = red_s + rem * 8;
            float4 rA = *(const float4*)(rp);
            float4 rB = *(const float4*)(rp + 4);
            a0 += rA.x; a1 += rA.y; a2 += rA.z; a3 += rA.w;
            a4 += rB.x; a5 += rB.y; a6 += rB.z; a7 += rB.w;

            float iv0 = sigm_(a0), fv0 = sigm_(a1), gv0 = tanh_(a2), ov0 = sigm_(a3);
            float iv1 = sigm_(a4), fv1 = sigm_(a5), gv1 = tanh_(a6), ov1 = sigm_(a7);
            c0 = fv0 * c0 + iv0 * gv0;
            c1 = fv1 * c1 + iv1 * gv1;
            float h0 = ov0 * tanh_(c0);
            float h1 = ov1 * tanh_(c1);

            float* hn = g_hbuf + (cur ^ 1) * (H_ * B_);
            *(float2*)(hn + (s * 32 + ty) * 256 + gb0 + 2 * tx) = make_float2(h0, h1);

            if (h_arch)
                *(float2*)(a_s + ty * 18 + 2 * tx) = make_float2(h0, h1);
            if (h_last && t == T_ - 1) {
                h_last[(gb0 + 2 * tx) * H_ + s * 32 + ty]     = h0;
                h_last[(gb0 + 2 * tx + 1) * H_ + s * 32 + ty] = h1;
            }
        }

        if (h_arch) {
            __syncthreads();
            int b2 = tid >> 5, u2 = tid & 31;
            h_arch[((size_t)t * 256 + gb0 + b2) * H_ + s * 32 + u2] = a_s[u2 * 18 + b2];
        }

        // Release h(t) + sync all 8 CTAs of the cluster (also a CTA barrier)
        asm volatile("barrier.cluster.arrive.aligned;\n" ::: "memory");
        asm volatile("barrier.cluster.wait.aligned;\n" ::: "memory");
    }
}

// ---------------- head: collapse W2@(W1 . + b1) + b2 into one linear map ----------------
__global__ void __launch_bounds__(256) head_pre_kernel(
    const float* __restrict__ W1, const float* __restrict__ b1,
    const float* __restrict__ W2, const float* __restrict__ b2)
{
    __shared__ float w2s[4 * 1280];
    const int tid = threadIdx.x;   // = hidden index h
    for (int idx = tid; idx < 4 * 1280; idx += 256) w2s[idx] = W2[idx];
    __syncthreads();

    float acc[4] = {0.f, 0.f, 0.f, 0.f};
    for (int j = 0; j < 1280; j++) {
        float w1v = W1[(size_t)j * 256 + tid];
#pragma unroll
        for (int o = 0; o < 4; o++) acc[o] = fmaf(w2s[o * 1280 + j], w1v, acc[o]);
    }
#pragma unroll
    for (int o = 0; o < 4; o++) g_weff[o * 256 + tid] = acc[o];

    if (tid < 4) {
        float bb = b2[tid];
        for (int j = 0; j < 1280; j++) bb = fmaf(w2s[tid * 1280 + j], b1[j], bb);
        g_beff[tid] = bb;
    }
}

__global__ void __launch_bounds__(256) head_final_kernel(float* __restrict__ out)
{
    int id = blockIdx.x * 256 + threadIdx.x;  // 0..1023
    int b = id >> 2, o = id & 3;
    float acc = g_beff[o];
    const float* lp = g_last + b * 256;
    const float* wp = g_weff + o * 256;
    for (int h = 0; h < 256; h++) acc = fmaf(lp[h], wp[h], acc);
    out[id] = acc;   // y[b][o], row-major [256,4]
}

// ---------------- launch ----------------
extern "C" void kernel_launch(void* const* d_in, const int* in_sizes, int n_in,
                              void* d_out, int out_size)
{
    const float* x    = (const float*)d_in[0];
    const float* Wih0 = (const float*)d_in[1];
    const float* Whh0 = (const float*)d_in[2];
    const float* bih0 = (const float*)d_in[3];
    const float* bhh0 = (const float*)d_in[4];
    const float* Wih1 = (const float*)d_in[5];
    const float* Whh1 = (const float*)d_in[6];
    const float* bih1 = (const float*)d_in[7];
    const float* bhh1 = (const float*)d_in[8];
    const float* W1   = (const float*)d_in[9];
    const float* b1   = (const float*)d_in[10];
    const float* W2   = (const float*)d_in[11];
    const float* b2   = (const float*)d_in[12];
    float* out = (float*)d_out;

    float *p_xg, *p_h1, *p_last;
    cudaGetSymbolAddress((void**)&p_xg, g_xg);
    cudaGetSymbolAddress((void**)&p_h1, g_h1);
    cudaGetSymbolAddress((void**)&p_last, g_last);

    cudaFuncSetAttribute(lstm_scan_kernel,
                         cudaFuncAttributeMaxDynamicSharedMemorySize, SCAN_SMEM);

    dim3 gemmGrid(8, 1024);  // N tiles x M tiles (M = 131072)
    dim3 scanGrid(8, 16);    // 8-CTA clusters x 16 batch groups

    // Layer 0: input projection (rows b*T+t), then scan (archives h1 as [t][b][v])
    gemm_bias_kernel<<<gemmGrid, 256>>>(x, Wih0, bih0, bhh0, p_xg, IDIM);
    lstm_scan_kernel<<<scanGrid, 512, SCAN_SMEM>>>(p_xg, Whh0, p_h1, nullptr, 0);

    // Layer 1: projection from h1 (rows t*B+b), then scan (keeps only last h)
    gemm_bias_kernel<<<gemmGrid, 256>>>(p_h1, Wih1, bih1, bhh1, p_xg, H_);
    lstm_scan_kernel<<<scanGrid, 512, SCAN_SMEM>>>(p_xg, Whh1, nullptr, p_last, 1);

    // Collapsed linear head
    head_pre_kernel<<<1, 256>>>(W1, b1, W2, b2);
    head_final_kernel<<<4, 256>>>(out);
}